// round 15
// baseline (speedup 1.0000x reference)
#include <cuda_runtime.h>
#include <cuda_fp16.h>
#include <cstdint>
#include <math.h>

// Problem constants
#define BATCH 4
#define SEQ   2048
#define DIM   768
#define HEADS 12
#define DHEAD 64
#define INNER 768
#define ROWS  (BATCH * SEQ)        // 8192
#define QKV_N (3 * INNER)          // 2304

// Scratch (allocation-free: __device__ globals) — all intermediates fp16
__device__ __align__(256) __half g_xn[ROWS * DIM];
__device__ __align__(256) __half g_qkv[ROWS * QKV_N];
__device__ __align__(256) __half g_attn[ROWS * INNER];
__device__ __align__(256) __half g_wtq[QKV_N * DIM];   // W_qkv^T [N,K]
__device__ __align__(256) __half g_wto[DIM * INNER];   // W_out^T [N,K]

// ---------------------------------------------------------------------------
// helpers (plain sm_80-era PTX — compiles for bare compute_103)
// ---------------------------------------------------------------------------
__device__ __forceinline__ uint32_t smem_u32(const void* p) {
    uint32_t a;
    asm("{ .reg .u64 t; cvta.to.shared.u64 t, %1; cvt.u32.u64 %0, t; }"
        : "=r"(a) : "l"(p));
    return a;
}

__device__ __forceinline__ void cp16(uint32_t dst, const void* src) {
    asm volatile("cp.async.cg.shared.global [%0], [%1], 16;"
                 :: "r"(dst), "l"(src));
}
#define CP_COMMIT() asm volatile("cp.async.commit_group;")
#define CP_WAIT0()  asm volatile("cp.async.wait_group 0;")
#define CP_WAIT1()  asm volatile("cp.async.wait_group 1;")

__device__ __forceinline__ void ldm4(uint32_t r[4], uint32_t a) {
    asm volatile("ldmatrix.sync.aligned.m8n8.x4.shared.b16 {%0,%1,%2,%3}, [%4];"
        : "=r"(r[0]), "=r"(r[1]), "=r"(r[2]), "=r"(r[3]) : "r"(a));
}
__device__ __forceinline__ void ldm4t(uint32_t r[4], uint32_t a) {
    asm volatile("ldmatrix.sync.aligned.m8n8.x4.trans.shared.b16 {%0,%1,%2,%3}, [%4];"
        : "=r"(r[0]), "=r"(r[1]), "=r"(r[2]), "=r"(r[3]) : "r"(a));
}

__device__ __forceinline__ void mma16(float c[4], const uint32_t a[4],
                                      uint32_t b0, uint32_t b1) {
    asm volatile(
        "mma.sync.aligned.m16n8k16.row.col.f32.f16.f16.f32 "
        "{%0,%1,%2,%3}, {%4,%5,%6,%7}, {%8,%9}, {%0,%1,%2,%3};"
        : "+f"(c[0]), "+f"(c[1]), "+f"(c[2]), "+f"(c[3])
        : "r"(a[0]), "r"(a[1]), "r"(a[2]), "r"(a[3]), "r"(b0), "r"(b1));
}

__device__ __forceinline__ float ex2(float x) {
    float r;
    asm("ex2.approx.f32 %0, %1;" : "=f"(r) : "f"(x));
    return r;
}

// ---------------------------------------------------------------------------
// Kernel 0 (fused prep): both weight transposes + LayerNorm in ONE launch.
// ---------------------------------------------------------------------------
#define TQ_BLKS (QKV_N / 32 * (DIM / 32))   // 1728
#define TO_BLKS (DIM / 32 * (DIM / 32))     // 576
#define PREP_BLKS (TQ_BLKS + TO_BLKS + ROWS)

__global__ __launch_bounds__(256) void prep_kernel(
    const float* __restrict__ Wq, __half* __restrict__ WqT,
    const float* __restrict__ Wo, __half* __restrict__ WoT,
    const float* __restrict__ x, const float* __restrict__ g,
    const float* __restrict__ b, __half* __restrict__ xn)
{
    __shared__ float t[32][33];
    const int blk = blockIdx.x;
    const int tid = threadIdx.x;

    if (blk < TQ_BLKS + TO_BLKS) {
        const int which = (blk >= TQ_BLKS);
        const int id    = which ? blk - TQ_BLKS : blk;
        const int Ccols = which ? DIM : QKV_N;
        const int nbx   = Ccols / 32;
        const float* W  = which ? Wo  : Wq;
        __half* Wt      = which ? WoT : WqT;
        const int c0 = (id % nbx) * 32, r0 = (id / nbx) * 32;

        const int xq = tid & 31, yq = tid >> 5;
        #pragma unroll
        for (int i = 0; i < 32; i += 8)
            t[yq + i][xq] = W[(size_t)(r0 + yq + i) * Ccols + c0 + xq];
        __syncthreads();
        #pragma unroll
        for (int i = 0; i < 32; i += 8)
            Wt[(size_t)(c0 + yq + i) * DIM + r0 + xq] =
                __float2half_rn(t[xq][yq + i]);
        return;
    }

    const int row = blk - (TQ_BLKS + TO_BLKS);
    const float* xr = x + (size_t)row * DIM;

    float v0 = xr[tid];
    float v1 = xr[tid + 256];
    float v2 = xr[tid + 512];
    float s  = v0 + v1 + v2;
    float ss = v0 * v0 + v1 * v1 + v2 * v2;

    #pragma unroll
    for (int m = 16; m; m >>= 1) {
        s  += __shfl_xor_sync(0xffffffffu, s, m);
        ss += __shfl_xor_sync(0xffffffffu, ss, m);
    }
    float* shs  = &t[0][0];
    float* shss = &t[1][0];
    float* stat = &t[2][0];
    const int w = tid >> 5, l = tid & 31;
    if (l == 0) { shs[w] = s; shss[w] = ss; }
    __syncthreads();
    if (tid == 0) {
        float S = 0.f, SS = 0.f;
        #pragma unroll
        for (int i = 0; i < 8; i++) { S += shs[i]; SS += shss[i]; }
        float mean = S * (1.f / DIM);
        float var  = SS * (1.f / DIM) - mean * mean;
        stat[0] = mean;
        stat[1] = rsqrtf(var + 1e-5f);
    }
    __syncthreads();
    const float mean = stat[0], rstd = stat[1];
    __half* xo = xn + (size_t)row * DIM;
    xo[tid]       = __float2half_rn((v0 - mean) * rstd * g[tid]       + b[tid]);
    xo[tid + 256] = __float2half_rn((v1 - mean) * rstd * g[tid + 256] + b[tid + 256]);
    xo[tid + 512] = __float2half_rn((v2 - mean) * rstd * g[tid + 512] + b[tid + 512]);
}

// ---------------------------------------------------------------------------
// Kernel 2: fp16 mma GEMM for QKV.  Block 256x128, 8 warps (4m x 2n),
// warp tile 64x64, BK=64, 3-stage cp.async ring, ONE sync per K-chunk.
// Row stride 72 halfs.  half output.  (R14 config — at ceiling.)
// ---------------------------------------------------------------------------
#define G2STR 72
#define G2_AS  (256 * G2STR)
#define G2_BS  (128 * G2STR)
#define G2_SMEM ((3 * G2_AS + 3 * G2_BS) * 2)   // 165888 bytes

__global__ __launch_bounds__(256) void gemm_h(
    const __half* __restrict__ A, const __half* __restrict__ Bt,
    const float* __restrict__ bias, __half* __restrict__ C, int N, int K)
{
    extern __shared__ __half gsm[];
    __half* As = gsm;
    __half* Bs = gsm + 3 * G2_AS;

    const int tid  = threadIdx.x;
    const int lane = tid & 31;
    const int wid  = tid >> 5;
    const int wm = (wid & 3) * 64;
    const int wn = (wid >> 2) * 64;
    const int qr = lane >> 2, qc = lane & 3;
    const int bx = blockIdx.x, by = blockIdx.y;

    const __half* Ab = A  + (size_t)by * 256 * K;
    const __half* Bb = Bt + (size_t)bx * 128 * K;

    const int lr  = tid >> 3;
    const int lc8 = (tid & 7) * 8;

    auto load_stage = [&](int st, int k0) {
        uint32_t au = smem_u32(As + st * G2_AS);
        uint32_t bu = smem_u32(Bs + st * G2_BS);
        #pragma unroll
        for (int j = 0; j < 8; j++) {
            const int r = lr + j * 32;
            cp16(au + (uint32_t)(r * G2STR + lc8) * 2,
                 Ab + (size_t)r * K + k0 + lc8);
        }
        #pragma unroll
        for (int j = 0; j < 4; j++) {
            const int r = lr + j * 32;
            cp16(bu + (uint32_t)(r * G2STR + lc8) * 2,
                 Bb + (size_t)r * K + k0 + lc8);
        }
        CP_COMMIT();
    };

    float acc[4][8][4];
    #pragma unroll
    for (int mi = 0; mi < 4; mi++)
        #pragma unroll
        for (int ni = 0; ni < 8; ni++)
            #pragma unroll
            for (int j = 0; j < 4; j++) acc[mi][ni][j] = 0.f;

    const int NC = K / 64;   // 12

    load_stage(0, 0);
    load_stage(1, 64);

    for (int kc = 0; kc < NC; kc++) {
        if (kc + 2 < NC) CP_WAIT1(); else CP_WAIT0();
        __syncthreads();
        if (kc + 2 < NC) load_stage((kc + 2) % 3, (kc + 2) * 64);

        const int st = kc % 3;
        const uint32_t a_base = smem_u32(As + st * G2_AS);
        const uint32_t b_base = smem_u32(Bs + st * G2_BS);

        #pragma unroll
        for (int ks = 0; ks < 4; ks++) {
            const int k0 = ks * 16;
            uint32_t af[4][4];
            #pragma unroll
            for (int mi = 0; mi < 4; mi++) {
                const uint32_t ad = a_base +
                    (uint32_t)((wm + mi * 16 + (lane & 15)) * G2STR
                               + k0 + ((lane >> 4) << 3)) * 2;
                ldm4(af[mi], ad);
            }
            #pragma unroll
            for (int np = 0; np < 4; np++) {
                uint32_t bf[4];
                const uint32_t bd = b_base +
                    (uint32_t)((wn + np * 16 + (lane & 7) + ((lane >> 4) << 3)) * G2STR
                               + k0 + (((lane >> 3) & 1) << 3)) * 2;
                ldm4(bf, bd);
                #pragma unroll
                for (int mi = 0; mi < 4; mi++) {
                    mma16(acc[mi][2 * np],     af[mi], bf[0], bf[1]);
                    mma16(acc[mi][2 * np + 1], af[mi], bf[2], bf[3]);
                }
            }
        }
    }

    const int cb = bx * 128 + wn;
    #pragma unroll
    for (int mi = 0; mi < 4; mi++)
        #pragma unroll
        for (int hf = 0; hf < 2; hf++) {
            const int row = by * 256 + wm + mi * 16 + qr + hf * 8;
            __half* Cp = C + (size_t)row * N + cb;
            #pragma unroll
            for (int ni = 0; ni < 8; ni++) {
                const int c = ni * 8 + 2 * qc;
                *(__half2*)(Cp + c) = __floats2half2_rn(
                    acc[mi][ni][hf * 2 + 0] + bias[cb + c],
                    acc[mi][ni][hf * 2 + 1] + bias[cb + c + 1]);
            }
        }
}

// ---------------------------------------------------------------------------
// Kernel 4: fp16 mma GEMM for out-projection.  Block 128x128, 8 warps,
// warp tile 32x64, BK=64, 2-stage, 2 CTAs/SM.  fp32 output.  (R14 config.)
// ---------------------------------------------------------------------------
#define GO_S   (128 * G2STR)
#define GO_SMEM ((4 * GO_S) * 2)   // 73728 bytes

__global__ __launch_bounds__(256) void gemm_o(
    const __half* __restrict__ A, const __half* __restrict__ Bt,
    const float* __restrict__ bias, float* __restrict__ C, int N, int K)
{
    extern __shared__ __half osm[];
    __half* As = osm;
    __half* Bs = osm + 2 * GO_S;

    const int tid  = threadIdx.x;
    const int lane = tid & 31;
    const int wid  = tid >> 5;
    const int wm = (wid >> 1) * 32;
    const int wn = (wid & 1) * 64;
    const int qr = lane >> 2, qc = lane & 3;
    const int bx = blockIdx.x, by = blockIdx.y;

    const __half* Ab = A  + (size_t)by * 128 * K;
    const __half* Bb = Bt + (size_t)bx * 128 * K;

    const int lr  = tid >> 3;
    const int lc8 = (tid & 7) * 8;

    auto load_stage = [&](int st, int k0) {
        uint32_t au = smem_u32(As + st * GO_S);
        uint32_t bu = smem_u32(Bs + st * GO_S);
        #pragma unroll
        for (int j = 0; j < 4; j++) {
            const int r = lr + j * 32;
            cp16(au + (uint32_t)(r * G2STR + lc8) * 2,
                 Ab + (size_t)r * K + k0 + lc8);
            cp16(bu + (uint32_t)(r * G2STR + lc8) * 2,
                 Bb + (size_t)r * K + k0 + lc8);
        }
        CP_COMMIT();
    };

    load_stage(0, 0);

    float acc[2][8][4];
    #pragma unroll
    for (int mi = 0; mi < 2; mi++)
        #pragma unroll
        for (int ni = 0; ni < 8; ni++)
            #pragma unroll
            for (int j = 0; j < 4; j++) acc[mi][ni][j] = 0.f;

    const int NC = K / 64;   // 12
    for (int kc = 0; kc < NC; kc++) {
        const int buf = kc & 1;
        if (kc + 1 < NC) {
            load_stage(buf ^ 1, (kc + 1) * 64);
            CP_WAIT1();
        } else {
            CP_WAIT0();
        }
        __syncthreads();

        const uint32_t a_base = smem_u32(As + buf * GO_S);
        const uint32_t b_base = smem_u32(Bs + buf * GO_S);
        #pragma unroll
        for (int ks = 0; ks < 4; ks++) {
            const int k0 = ks * 16;
            uint32_t af[2][4];
            #pragma unroll
            for (int mi = 0; mi < 2; mi++) {
                const uint32_t ad = a_base +
                    (uint32_t)((wm + mi * 16 + (lane & 15)) * G2STR
                               + k0 + ((lane >> 4) << 3)) * 2;
                ldm4(af[mi], ad);
            }
            #pragma unroll
            for (int np = 0; np < 4; np++) {
                uint32_t bf[4];
                const uint32_t bd = b_base +
                    (uint32_t)((wn + np * 16 + (lane & 7) + ((lane >> 4) << 3)) * G2STR
                               + k0 + (((lane >> 3) & 1) << 3)) * 2;
                ldm4(bf, bd);
                mma16(acc[0][2 * np],     af[0], bf[0], bf[1]);
                mma16(acc[0][2 * np + 1], af[0], bf[2], bf[3]);
                mma16(acc[1][2 * np],     af[1], bf[0], bf[1]);
                mma16(acc[1][2 * np + 1], af[1], bf[2], bf[3]);
            }
        }
        __syncthreads();
    }

    const int cb = bx * 128 + wn;
    #pragma unroll
    for (int mi = 0; mi < 2; mi++)
        #pragma unroll
        for (int hf = 0; hf < 2; hf++) {
            const int row = by * 128 + wm + mi * 16 + qr + hf * 8;
            float* Cp = C + (size_t)row * N + cb;
            #pragma unroll
            for (int ni = 0; ni < 8; ni++) {
                const int c = ni * 8 + 2 * qc;
                float2 v;
                v.x = acc[mi][ni][hf * 2 + 0] + bias[cb + c];
                v.y = acc[mi][ni][hf * 2 + 1] + bias[cb + c + 1];
                *(float2*)(Cp + c) = v;
            }
        }
}

// ---------------------------------------------------------------------------
// Kernel 3: fp16 flash attention, warp-M=32.  BR=128, BC=64, d=64.
// 4 warps (128 thr); each warp owns TWO m16 row-blocks (32 query rows), so
// every K/V fragment load feeds 2 mma (LDSM:mma = 0.5, was 1.0).
// Register-resident P, warp-uniform rescale skip, 2-stage cp.async K/V.
// ---------------------------------------------------------------------------
#define FSTR 72
#define SC_L2E 0.18033688011112042f          // 0.125 * log2(e)

__global__ __launch_bounds__(128) void flash_h(
    const __half* __restrict__ qkv, __half* __restrict__ out)
{
    extern __shared__ __half fs[];
    __half* Qs = fs;                              // 128 x FSTR
    __half* Kst[2] = { fs + 128 * FSTR,           // 64 x FSTR each
                       fs + 192 * FSTR };
    __half* Vst[2] = { fs + 256 * FSTR,
                       fs + 320 * FSTR };

    const int tid  = threadIdx.x;
    const int lane = tid & 31;
    const int wid  = tid >> 5;        // 0..3
    const int qr = lane >> 2, qc = lane & 3;
    const int m0 = wid * 32;          // warp owns rows m0..m0+31

    const int qt = blockIdx.x;        // 0..15 (128-row query tiles)
    const int bh = blockIdx.y;        // 0..47
    const int bb = bh / HEADS, h = bh % HEADS;

    const __half* base = qkv + (size_t)bb * SEQ * QKV_N;
    const __half* qb = base + h * DHEAD;
    const __half* kb = base + INNER + h * DHEAD;
    const __half* vb = base + 2 * INNER + h * DHEAD;

    const uint32_t q_u = smem_u32(Qs);
    const uint32_t k_u[2] = { smem_u32(Kst[0]), smem_u32(Kst[1]) };
    const uint32_t v_u[2] = { smem_u32(Vst[0]), smem_u32(Vst[1]) };

    // prologue: Q tile (128 x 64) + K/V stage 0
    #pragma unroll
    for (int j = 0; j < 8; j++) {
        const int i = tid + j * 128;           // 0..1023
        const int r = i >> 3, cg = (i & 7) * 8;
        cp16(q_u + (uint32_t)(r * FSTR + cg) * 2,
             qb + (size_t)(qt * 128 + r) * QKV_N + cg);
    }
    #pragma unroll
    for (int j = 0; j < 4; j++) {
        const int i = tid + j * 128;
        const int r = i >> 3, cg = (i & 7) * 8;
        const size_t off = (size_t)r * QKV_N + cg;
        cp16(k_u[0] + (uint32_t)(r * FSTR + cg) * 2, kb + off);
        cp16(v_u[0] + (uint32_t)(r * FSTR + cg) * 2, vb + off);
    }
    CP_COMMIT();

    float mrow[4] = {-1e30f, -1e30f, -1e30f, -1e30f};
    float lrow[4] = {0.f, 0.f, 0.f, 0.f};
    float o[2][8][4];
    #pragma unroll
    for (int rb = 0; rb < 2; rb++)
        #pragma unroll
        for (int ni = 0; ni < 8; ni++)
            #pragma unroll
            for (int j = 0; j < 4; j++) o[rb][ni][j] = 0.f;

    uint32_t qf[2][4][4];
    const int NT = SEQ / 64;

    for (int t = 0; t < NT; t++) {
        const int buf = t & 1;
        if (t + 1 < NT) {
            #pragma unroll
            for (int j = 0; j < 4; j++) {
                const int i = tid + j * 128;
                const int r = i >> 3, cg = (i & 7) * 8;
                const size_t off = (size_t)((t + 1) * 64 + r) * QKV_N + cg;
                cp16(k_u[buf ^ 1] + (uint32_t)(r * FSTR + cg) * 2, kb + off);
                cp16(v_u[buf ^ 1] + (uint32_t)(r * FSTR + cg) * 2, vb + off);
            }
            CP_COMMIT();
            CP_WAIT1();
        } else {
            CP_WAIT0();
        }
        __syncthreads();

        if (t == 0) {
            #pragma unroll
            for (int rb = 0; rb < 2; rb++)
                #pragma unroll
                for (int ks = 0; ks < 4; ks++)
                    ldm4(qf[rb][ks],
                         q_u + (uint32_t)((m0 + rb * 16 + (lane & 15)) * FSTR
                               + ks * 16 + ((lane >> 4) << 3)) * 2);
        }

        // ---- S = Q @ K^T (two row-blocks share each K fragment) ----
        float s[2][8][4];
        #pragma unroll
        for (int rb = 0; rb < 2; rb++)
            #pragma unroll
            for (int ni = 0; ni < 8; ni++)
                #pragma unroll
                for (int j = 0; j < 4; j++) s[rb][ni][j] = 0.f;

        #pragma unroll
        for (int ks = 0; ks < 4; ks++) {
            const int k0 = ks * 16;
            #pragma unroll
            for (int np = 0; np < 4; np++) {
                uint32_t bf[4];
                const uint32_t bd = k_u[buf] +
                    (uint32_t)((np * 16 + (lane & 7) + ((lane >> 4) << 3)) * FSTR
                               + k0 + (((lane >> 3) & 1) << 3)) * 2;
                ldm4(bf, bd);
                #pragma unroll
                for (int rb = 0; rb < 2; rb++) {
                    mma16(s[rb][2 * np],     qf[rb][ks], bf[0], bf[1]);
                    mma16(s[rb][2 * np + 1], qf[rb][ks], bf[2], bf[3]);
                }
            }
        }

        // ---- online softmax in exp2 domain (per row-block) ----
        float al[4];
        #pragma unroll
        for (int rb = 0; rb < 2; rb++) {
            #pragma unroll
            for (int ni = 0; ni < 8; ni++)
                #pragma unroll
                for (int j = 0; j < 4; j++) s[rb][ni][j] *= SC_L2E;

            float mx0 = -1e30f, mx1 = -1e30f;
            #pragma unroll
            for (int ni = 0; ni < 8; ni++) {
                mx0 = fmaxf(mx0, fmaxf(s[rb][ni][0], s[rb][ni][1]));
                mx1 = fmaxf(mx1, fmaxf(s[rb][ni][2], s[rb][ni][3]));
            }
            mx0 = fmaxf(mx0, __shfl_xor_sync(0xffffffffu, mx0, 1));
            mx0 = fmaxf(mx0, __shfl_xor_sync(0xffffffffu, mx0, 2));
            mx1 = fmaxf(mx1, __shfl_xor_sync(0xffffffffu, mx1, 1));
            mx1 = fmaxf(mx1, __shfl_xor_sync(0xffffffffu, mx1, 2));

            const float mn0 = fmaxf(mrow[2 * rb],     mx0);
            const float mn1 = fmaxf(mrow[2 * rb + 1], mx1);
            al[2 * rb]     = ex2(mrow[2 * rb]     - mn0);
            al[2 * rb + 1] = ex2(mrow[2 * rb + 1] - mn1);
            mrow[2 * rb] = mn0; mrow[2 * rb + 1] = mn1;

            float sum0 = 0.f, sum1 = 0.f;
            #pragma unroll
            for (int ni = 0; ni < 8; ni++) {
                s[rb][ni][0] = ex2(s[rb][ni][0] - mn0); sum0 += s[rb][ni][0];
                s[rb][ni][1] = ex2(s[rb][ni][1] - mn0); sum0 += s[rb][ni][1];
                s[rb][ni][2] = ex2(s[rb][ni][2] - mn1); sum1 += s[rb][ni][2];
                s[rb][ni][3] = ex2(s[rb][ni][3] - mn1); sum1 += s[rb][ni][3];
            }
            sum0 += __shfl_xor_sync(0xffffffffu, sum0, 1);
            sum0 += __shfl_xor_sync(0xffffffffu, sum0, 2);
            sum1 += __shfl_xor_sync(0xffffffffu, sum1, 1);
            sum1 += __shfl_xor_sync(0xffffffffu, sum1, 2);
            lrow[2 * rb]     = lrow[2 * rb]     * al[2 * rb]     + sum0;
            lrow[2 * rb + 1] = lrow[2 * rb + 1] * al[2 * rb + 1] + sum1;
        }

        if (__any_sync(0xffffffffu, (al[0] != 1.f) | (al[1] != 1.f) |
                                    (al[2] != 1.f) | (al[3] != 1.f))) {
            #pragma unroll
            for (int rb = 0; rb < 2; rb++)
                #pragma unroll
                for (int ni = 0; ni < 8; ni++) {
                    o[rb][ni][0] *= al[2 * rb];     o[rb][ni][1] *= al[2 * rb];
                    o[rb][ni][2] *= al[2 * rb + 1]; o[rb][ni][3] *= al[2 * rb + 1];
                }
        }

        // ---- O += P @ V : P A-fragments packed directly from S C-frags;
        //      each V fragment feeds both row-blocks ----
        #pragma unroll
        for (int ks = 0; ks < 4; ks++) {
            uint32_t pf[2][4];
            #pragma unroll
            for (int rb = 0; rb < 2; rb++) {
                asm("cvt.rn.f16x2.f32 %0, %1, %2;" : "=r"(pf[rb][0])
                    : "f"(s[rb][2 * ks][1]),     "f"(s[rb][2 * ks][0]));
                asm("cvt.rn.f16x2.f32 %0, %1, %2;" : "=r"(pf[rb][1])
                    : "f"(s[rb][2 * ks][3]),     "f"(s[rb][2 * ks][2]));
                asm("cvt.rn.f16x2.f32 %0, %1, %2;" : "=r"(pf[rb][2])
                    : "f"(s[rb][2 * ks + 1][1]), "f"(s[rb][2 * ks + 1][0]));
                asm("cvt.rn.f16x2.f32 %0, %1, %2;" : "=r"(pf[rb][3])
                    : "f"(s[rb][2 * ks + 1][3]), "f"(s[rb][2 * ks + 1][2]));
            }
            #pragma unroll
            for (int np = 0; np < 4; np++) {
                uint32_t vf[4];
                const uint32_t vd = v_u[buf] +
                    (uint32_t)((ks * 16 + (lane & 7) + (((lane >> 3) & 1) << 3)) * FSTR
                               + np * 16 + ((lane >> 4) << 3)) * 2;
                ldm4t(vf, vd);
                #pragma unroll
                for (int rb = 0; rb < 2; rb++) {
                    mma16(o[rb][2 * np],     pf[rb], vf[0], vf[1]);
                    mma16(o[rb][2 * np + 1], pf[rb], vf[2], vf[3]);
                }
            }
        }
        __syncthreads();
    }

    // ---- normalize + store (half) into [b, n, h*64 + d] ----
    #pragma unroll
    for (int rb = 0; rb < 2; rb++) {
        const float inv0 = 1.f / lrow[2 * rb];
        const float inv1 = 1.f / lrow[2 * rb + 1];
        const size_t n0 = (size_t)bb * SEQ + qt * 128 + m0 + rb * 16 + qr;
        #pragma unroll
        for (int ni = 0; ni < 8; ni++) {
            const int c = h * DHEAD + ni * 8 + 2 * qc;
            *(__half2*)(out + n0 * INNER + c) =
                __floats2half2_rn(o[rb][ni][0] * inv0, o[rb][ni][1] * inv0);
            *(__half2*)(out + (n0 + 8) * INNER + c) =
                __floats2half2_rn(o[rb][ni][2] * inv1, o[rb][ni][3] * inv1);
        }
    }
}

// ---------------------------------------------------------------------------
extern "C" void kernel_launch(void* const* d_in, const int* in_sizes, int n_in,
                              void* d_out, int out_size)
{
    const float* x     = (const float*)d_in[0];
    const float* ln_g  = (const float*)d_in[1];
    const float* ln_b  = (const float*)d_in[2];
    const float* W_qkv = (const float*)d_in[3];
    const float* b_qkv = (const float*)d_in[4];
    const float* W_out = (const float*)d_in[5];
    const float* b_out = (const float*)d_in[6];
    float* out = (float*)d_out;

    __half *xn, *qkv, *attn, *wtq, *wto;
    cudaGetSymbolAddress((void**)&xn,   g_xn);
    cudaGetSymbolAddress((void**)&qkv,  g_qkv);
    cudaGetSymbolAddress((void**)&attn, g_attn);
    cudaGetSymbolAddress((void**)&wtq,  g_wtq);
    cudaGetSymbolAddress((void**)&wto,  g_wto);

    const int flash_smem = (128 + 4 * 64) * FSTR * (int)sizeof(__half); // 55296
    cudaFuncSetAttribute(gemm_h, cudaFuncAttributeMaxDynamicSharedMemorySize,
                         G2_SMEM);
    cudaFuncSetAttribute(gemm_o, cudaFuncAttributeMaxDynamicSharedMemorySize,
                         GO_SMEM);
    cudaFuncSetAttribute(flash_h, cudaFuncAttributeMaxDynamicSharedMemorySize,
                         flash_smem);

    // 0) fused prep: both weight transposes + LayerNorm, one launch
    prep_kernel<<<PREP_BLKS, 256>>>(W_qkv, wtq, W_out, wto,
                                    x, ln_g, ln_b, xn);

    // 1) QKV projection (fp16 mma, 256x128 tiles, BK=64, half out)
    gemm_h<<<dim3(QKV_N / 128, ROWS / 256), 256, G2_SMEM>>>(
        xn, wtq, b_qkv, qkv, QKV_N, DIM);

    // 2) attention (fp16 flash, warp-M=32, BR=128, half out)
    flash_h<<<dim3(SEQ / 128, BATCH * HEADS), 128, flash_smem>>>(qkv, attn);

    // 3) output projection (fp16 mma, 128x128 tiles, BK=64, fp32 out)
    gemm_o<<<dim3(DIM / 128, ROWS / 128), 256, GO_SMEM>>>(
        attn, wto, b_out, out, DIM, INNER);
}

// round 17
// speedup vs baseline: 1.0172x; 1.0172x over previous
#include <cuda_runtime.h>
#include <cuda_fp16.h>
#include <cstdint>
#include <math.h>

// Problem constants
#define BATCH 4
#define SEQ   2048
#define DIM   768
#define HEADS 12
#define DHEAD 64
#define INNER 768
#define ROWS  (BATCH * SEQ)        // 8192
#define QKV_N (3 * INNER)          // 2304

// Scratch (allocation-free: __device__ globals) — all intermediates fp16
__device__ __align__(256) __half g_xn[ROWS * DIM];
__device__ __align__(256) __half g_qkv[ROWS * QKV_N];
__device__ __align__(256) __half g_attn[ROWS * INNER];
__device__ __align__(256) __half g_wtq[QKV_N * DIM];   // W_qkv^T [N,K]
__device__ __align__(256) __half g_wto[DIM * INNER];   // W_out^T [N,K]

// ---------------------------------------------------------------------------
// helpers (plain sm_80-era PTX — compiles for bare compute_103)
// ---------------------------------------------------------------------------
__device__ __forceinline__ uint32_t smem_u32(const void* p) {
    uint32_t a;
    asm("{ .reg .u64 t; cvta.to.shared.u64 t, %1; cvt.u32.u64 %0, t; }"
        : "=r"(a) : "l"(p));
    return a;
}

__device__ __forceinline__ void cp16(uint32_t dst, const void* src) {
    asm volatile("cp.async.cg.shared.global [%0], [%1], 16;"
                 :: "r"(dst), "l"(src));
}
#define CP_COMMIT() asm volatile("cp.async.commit_group;")
#define CP_WAIT0()  asm volatile("cp.async.wait_group 0;")
#define CP_WAIT1()  asm volatile("cp.async.wait_group 1;")

__device__ __forceinline__ void ldm4(uint32_t r[4], uint32_t a) {
    asm volatile("ldmatrix.sync.aligned.m8n8.x4.shared.b16 {%0,%1,%2,%3}, [%4];"
        : "=r"(r[0]), "=r"(r[1]), "=r"(r[2]), "=r"(r[3]) : "r"(a));
}
__device__ __forceinline__ void ldm4t(uint32_t r[4], uint32_t a) {
    asm volatile("ldmatrix.sync.aligned.m8n8.x4.trans.shared.b16 {%0,%1,%2,%3}, [%4];"
        : "=r"(r[0]), "=r"(r[1]), "=r"(r[2]), "=r"(r[3]) : "r"(a));
}

__device__ __forceinline__ void mma16(float c[4], const uint32_t a[4],
                                      uint32_t b0, uint32_t b1) {
    asm volatile(
        "mma.sync.aligned.m16n8k16.row.col.f32.f16.f16.f32 "
        "{%0,%1,%2,%3}, {%4,%5,%6,%7}, {%8,%9}, {%0,%1,%2,%3};"
        : "+f"(c[0]), "+f"(c[1]), "+f"(c[2]), "+f"(c[3])
        : "r"(a[0]), "r"(a[1]), "r"(a[2]), "r"(a[3]), "r"(b0), "r"(b1));
}

__device__ __forceinline__ float ex2(float x) {
    float r;
    asm("ex2.approx.f32 %0, %1;" : "=f"(r) : "f"(x));
    return r;
}

// ---------------------------------------------------------------------------
// Kernel 0 (fused prep): both weight transposes + LayerNorm in ONE launch.
// ---------------------------------------------------------------------------
#define TQ_BLKS (QKV_N / 32 * (DIM / 32))   // 1728
#define TO_BLKS (DIM / 32 * (DIM / 32))     // 576
#define PREP_BLKS (TQ_BLKS + TO_BLKS + ROWS)

__global__ __launch_bounds__(256) void prep_kernel(
    const float* __restrict__ Wq, __half* __restrict__ WqT,
    const float* __restrict__ Wo, __half* __restrict__ WoT,
    const float* __restrict__ x, const float* __restrict__ g,
    const float* __restrict__ b, __half* __restrict__ xn)
{
    __shared__ float t[32][33];
    const int blk = blockIdx.x;
    const int tid = threadIdx.x;

    if (blk < TQ_BLKS + TO_BLKS) {
        const int which = (blk >= TQ_BLKS);
        const int id    = which ? blk - TQ_BLKS : blk;
        const int Ccols = which ? DIM : QKV_N;
        const int nbx   = Ccols / 32;
        const float* W  = which ? Wo  : Wq;
        __half* Wt      = which ? WoT : WqT;
        const int c0 = (id % nbx) * 32, r0 = (id / nbx) * 32;

        const int xq = tid & 31, yq = tid >> 5;
        #pragma unroll
        for (int i = 0; i < 32; i += 8)
            t[yq + i][xq] = W[(size_t)(r0 + yq + i) * Ccols + c0 + xq];
        __syncthreads();
        #pragma unroll
        for (int i = 0; i < 32; i += 8)
            Wt[(size_t)(c0 + yq + i) * DIM + r0 + xq] =
                __float2half_rn(t[xq][yq + i]);
        return;
    }

    const int row = blk - (TQ_BLKS + TO_BLKS);
    const float* xr = x + (size_t)row * DIM;

    float v0 = xr[tid];
    float v1 = xr[tid + 256];
    float v2 = xr[tid + 512];
    float s  = v0 + v1 + v2;
    float ss = v0 * v0 + v1 * v1 + v2 * v2;

    #pragma unroll
    for (int m = 16; m; m >>= 1) {
        s  += __shfl_xor_sync(0xffffffffu, s, m);
        ss += __shfl_xor_sync(0xffffffffu, ss, m);
    }
    float* shs  = &t[0][0];
    float* shss = &t[1][0];
    float* stat = &t[2][0];
    const int w = tid >> 5, l = tid & 31;
    if (l == 0) { shs[w] = s; shss[w] = ss; }
    __syncthreads();
    if (tid == 0) {
        float S = 0.f, SS = 0.f;
        #pragma unroll
        for (int i = 0; i < 8; i++) { S += shs[i]; SS += shss[i]; }
        float mean = S * (1.f / DIM);
        float var  = SS * (1.f / DIM) - mean * mean;
        stat[0] = mean;
        stat[1] = rsqrtf(var + 1e-5f);
    }
    __syncthreads();
    const float mean = stat[0], rstd = stat[1];
    __half* xo = xn + (size_t)row * DIM;
    xo[tid]       = __float2half_rn((v0 - mean) * rstd * g[tid]       + b[tid]);
    xo[tid + 256] = __float2half_rn((v1 - mean) * rstd * g[tid + 256] + b[tid + 256]);
    xo[tid + 512] = __float2half_rn((v2 - mean) * rstd * g[tid + 512] + b[tid + 512]);
}

// ---------------------------------------------------------------------------
// Kernel 2: fp16 mma GEMM for QKV.  Block 256x128, 8 warps (4m x 2n),
// warp tile 64x64, BK=64, 3-stage cp.async ring, ONE sync per K-chunk.
// Row stride 72 halfs.  half output.  (R14 config — at ceiling.)
// ---------------------------------------------------------------------------
#define G2STR 72
#define G2_AS  (256 * G2STR)
#define G2_BS  (128 * G2STR)
#define G2_SMEM ((3 * G2_AS + 3 * G2_BS) * 2)   // 165888 bytes

__global__ __launch_bounds__(256) void gemm_h(
    const __half* __restrict__ A, const __half* __restrict__ Bt,
    const float* __restrict__ bias, __half* __restrict__ C, int N, int K)
{
    extern __shared__ __half gsm[];
    __half* As = gsm;
    __half* Bs = gsm + 3 * G2_AS;

    const int tid  = threadIdx.x;
    const int lane = tid & 31;
    const int wid  = tid >> 5;
    const int wm = (wid & 3) * 64;
    const int wn = (wid >> 2) * 64;
    const int qr = lane >> 2, qc = lane & 3;
    const int bx = blockIdx.x, by = blockIdx.y;

    const __half* Ab = A  + (size_t)by * 256 * K;
    const __half* Bb = Bt + (size_t)bx * 128 * K;

    const int lr  = tid >> 3;
    const int lc8 = (tid & 7) * 8;

    auto load_stage = [&](int st, int k0) {
        uint32_t au = smem_u32(As + st * G2_AS);
        uint32_t bu = smem_u32(Bs + st * G2_BS);
        #pragma unroll
        for (int j = 0; j < 8; j++) {
            const int r = lr + j * 32;
            cp16(au + (uint32_t)(r * G2STR + lc8) * 2,
                 Ab + (size_t)r * K + k0 + lc8);
        }
        #pragma unroll
        for (int j = 0; j < 4; j++) {
            const int r = lr + j * 32;
            cp16(bu + (uint32_t)(r * G2STR + lc8) * 2,
                 Bb + (size_t)r * K + k0 + lc8);
        }
        CP_COMMIT();
    };

    float acc[4][8][4];
    #pragma unroll
    for (int mi = 0; mi < 4; mi++)
        #pragma unroll
        for (int ni = 0; ni < 8; ni++)
            #pragma unroll
            for (int j = 0; j < 4; j++) acc[mi][ni][j] = 0.f;

    const int NC = K / 64;   // 12

    load_stage(0, 0);
    load_stage(1, 64);

    for (int kc = 0; kc < NC; kc++) {
        if (kc + 2 < NC) CP_WAIT1(); else CP_WAIT0();
        __syncthreads();
        if (kc + 2 < NC) load_stage((kc + 2) % 3, (kc + 2) * 64);

        const int st = kc % 3;
        const uint32_t a_base = smem_u32(As + st * G2_AS);
        const uint32_t b_base = smem_u32(Bs + st * G2_BS);

        #pragma unroll
        for (int ks = 0; ks < 4; ks++) {
            const int k0 = ks * 16;
            uint32_t af[4][4];
            #pragma unroll
            for (int mi = 0; mi < 4; mi++) {
                const uint32_t ad = a_base +
                    (uint32_t)((wm + mi * 16 + (lane & 15)) * G2STR
                               + k0 + ((lane >> 4) << 3)) * 2;
                ldm4(af[mi], ad);
            }
            #pragma unroll
            for (int np = 0; np < 4; np++) {
                uint32_t bf[4];
                const uint32_t bd = b_base +
                    (uint32_t)((wn + np * 16 + (lane & 7) + ((lane >> 4) << 3)) * G2STR
                               + k0 + (((lane >> 3) & 1) << 3)) * 2;
                ldm4(bf, bd);
                #pragma unroll
                for (int mi = 0; mi < 4; mi++) {
                    mma16(acc[mi][2 * np],     af[mi], bf[0], bf[1]);
                    mma16(acc[mi][2 * np + 1], af[mi], bf[2], bf[3]);
                }
            }
        }
    }

    const int cb = bx * 128 + wn;
    #pragma unroll
    for (int mi = 0; mi < 4; mi++)
        #pragma unroll
        for (int hf = 0; hf < 2; hf++) {
            const int row = by * 256 + wm + mi * 16 + qr + hf * 8;
            __half* Cp = C + (size_t)row * N + cb;
            #pragma unroll
            for (int ni = 0; ni < 8; ni++) {
                const int c = ni * 8 + 2 * qc;
                *(__half2*)(Cp + c) = __floats2half2_rn(
                    acc[mi][ni][hf * 2 + 0] + bias[cb + c],
                    acc[mi][ni][hf * 2 + 1] + bias[cb + c + 1]);
            }
        }
}

// ---------------------------------------------------------------------------
// Kernel 4: fp16 mma GEMM for out-projection.  Block 128x128, 8 warps,
// warp tile 32x64, BK=64, NOW 3-stage single-sync ring (same structure that
// won in gemm_h; removes one __syncthreads per K-chunk).  2 CTAs/SM
// (reg-bound), smem 110.6 KB.  fp32 output.
// ---------------------------------------------------------------------------
#define GO_S   (128 * G2STR)
#define GO_SMEM ((6 * GO_S) * 2)   // 3 stages x (A+B) = 110592 bytes

__global__ __launch_bounds__(256) void gemm_o(
    const __half* __restrict__ A, const __half* __restrict__ Bt,
    const float* __restrict__ bias, float* __restrict__ C, int N, int K)
{
    extern __shared__ __half osm[];
    __half* As = osm;                 // 3 stages of 128 x G2STR
    __half* Bs = osm + 3 * GO_S;      // 3 stages of 128 x G2STR

    const int tid  = threadIdx.x;
    const int lane = tid & 31;
    const int wid  = tid >> 5;
    const int wm = (wid >> 1) * 32;
    const int wn = (wid & 1) * 64;
    const int qr = lane >> 2, qc = lane & 3;
    const int bx = blockIdx.x, by = blockIdx.y;

    const __half* Ab = A  + (size_t)by * 128 * K;
    const __half* Bb = Bt + (size_t)bx * 128 * K;

    const int lr  = tid >> 3;
    const int lc8 = (tid & 7) * 8;

    auto load_stage = [&](int st, int k0) {
        uint32_t au = smem_u32(As + st * GO_S);
        uint32_t bu = smem_u32(Bs + st * GO_S);
        #pragma unroll
        for (int j = 0; j < 4; j++) {
            const int r = lr + j * 32;
            cp16(au + (uint32_t)(r * G2STR + lc8) * 2,
                 Ab + (size_t)r * K + k0 + lc8);
            cp16(bu + (uint32_t)(r * G2STR + lc8) * 2,
                 Bb + (size_t)r * K + k0 + lc8);
        }
        CP_COMMIT();
    };

    float acc[2][8][4];
    #pragma unroll
    for (int mi = 0; mi < 2; mi++)
        #pragma unroll
        for (int ni = 0; ni < 8; ni++)
            #pragma unroll
            for (int j = 0; j < 4; j++) acc[mi][ni][j] = 0.f;

    const int NC = K / 64;   // 12

    load_stage(0, 0);
    load_stage(1, 64);

    for (int kc = 0; kc < NC; kc++) {
        if (kc + 2 < NC) CP_WAIT1(); else CP_WAIT0();
        __syncthreads();
        if (kc + 2 < NC) load_stage((kc + 2) % 3, (kc + 2) * 64);

        const int st = kc % 3;
        const uint32_t a_base = smem_u32(As + st * GO_S);
        const uint32_t b_base = smem_u32(Bs + st * GO_S);
        #pragma unroll
        for (int ks = 0; ks < 4; ks++) {
            const int k0 = ks * 16;
            uint32_t af[2][4];
            #pragma unroll
            for (int mi = 0; mi < 2; mi++) {
                const uint32_t ad = a_base +
                    (uint32_t)((wm + mi * 16 + (lane & 15)) * G2STR
                               + k0 + ((lane >> 4) << 3)) * 2;
                ldm4(af[mi], ad);
            }
            #pragma unroll
            for (int np = 0; np < 4; np++) {
                uint32_t bf[4];
                const uint32_t bd = b_base +
                    (uint32_t)((wn + np * 16 + (lane & 7) + ((lane >> 4) << 3)) * G2STR
                               + k0 + (((lane >> 3) & 1) << 3)) * 2;
                ldm4(bf, bd);
                mma16(acc[0][2 * np],     af[0], bf[0], bf[1]);
                mma16(acc[0][2 * np + 1], af[0], bf[2], bf[3]);
                mma16(acc[1][2 * np],     af[1], bf[0], bf[1]);
                mma16(acc[1][2 * np + 1], af[1], bf[2], bf[3]);
            }
        }
    }

    const int cb = bx * 128 + wn;
    #pragma unroll
    for (int mi = 0; mi < 2; mi++)
        #pragma unroll
        for (int hf = 0; hf < 2; hf++) {
            const int row = by * 128 + wm + mi * 16 + qr + hf * 8;
            float* Cp = C + (size_t)row * N + cb;
            #pragma unroll
            for (int ni = 0; ni < 8; ni++) {
                const int c = ni * 8 + 2 * qc;
                float2 v;
                v.x = acc[mi][ni][hf * 2 + 0] + bias[cb + c];
                v.y = acc[mi][ni][hf * 2 + 1] + bias[cb + c + 1];
                *(float2*)(Cp + c) = v;
            }
        }
}

// ---------------------------------------------------------------------------
// Kernel 3: fp16 flash attention (EXACT R14 config — best measured).
// BR=64, BC=64, d=64.  4 warps; warp owns 16 query rows.  Register-resident
// P.  Warp-uniform rescale skip.  2-stage cp.async K/V.  4 CTAs/SM.
// ---------------------------------------------------------------------------
#define FSTR 72
#define SC_L2E 0.18033688011112042f          // 0.125 * log2(e)

__global__ __launch_bounds__(128) void flash_h(
    const __half* __restrict__ qkv, __half* __restrict__ out)
{
    extern __shared__ __half fs[];
    __half* Qs = fs;
    __half* Kst[2] = { fs + 1 * 64 * FSTR, fs + 2 * 64 * FSTR };
    __half* Vst[2] = { fs + 3 * 64 * FSTR, fs + 4 * 64 * FSTR };

    const int tid  = threadIdx.x;
    const int lane = tid & 31;
    const int wid  = tid >> 5;
    const int qr = lane >> 2, qc = lane & 3;
    const int m0 = wid * 16;

    const int qt = blockIdx.x;
    const int bh = blockIdx.y;
    const int bb = bh / HEADS, h = bh % HEADS;

    const __half* base = qkv + (size_t)bb * SEQ * QKV_N;
    const __half* qb = base + h * DHEAD;
    const __half* kb = base + INNER + h * DHEAD;
    const __half* vb = base + 2 * INNER + h * DHEAD;

    const uint32_t q_u = smem_u32(Qs);
    const uint32_t k_u[2] = { smem_u32(Kst[0]), smem_u32(Kst[1]) };
    const uint32_t v_u[2] = { smem_u32(Vst[0]), smem_u32(Vst[1]) };

    #pragma unroll
    for (int j = 0; j < 4; j++) {
        const int i = tid + j * 128;
        const int r = i >> 3, cg = (i & 7) * 8;
        cp16(q_u + (uint32_t)(r * FSTR + cg) * 2,
             qb + (size_t)(qt * 64 + r) * QKV_N + cg);
    }
    #pragma unroll
    for (int j = 0; j < 4; j++) {
        const int i = tid + j * 128;
        const int r = i >> 3, cg = (i & 7) * 8;
        const size_t off = (size_t)r * QKV_N + cg;
        cp16(k_u[0] + (uint32_t)(r * FSTR + cg) * 2, kb + off);
        cp16(v_u[0] + (uint32_t)(r * FSTR + cg) * 2, vb + off);
    }
    CP_COMMIT();

    float mrow[2] = {-1e30f, -1e30f};
    float lrow[2] = {0.f, 0.f};
    float o[8][4];
    #pragma unroll
    for (int ni = 0; ni < 8; ni++)
        #pragma unroll
        for (int j = 0; j < 4; j++) o[ni][j] = 0.f;

    uint32_t qf[4][4];
    const int NT = SEQ / 64;

    for (int t = 0; t < NT; t++) {
        const int buf = t & 1;
        if (t + 1 < NT) {
            #pragma unroll
            for (int j = 0; j < 4; j++) {
                const int i = tid + j * 128;
                const int r = i >> 3, cg = (i & 7) * 8;
                const size_t off = (size_t)((t + 1) * 64 + r) * QKV_N + cg;
                cp16(k_u[buf ^ 1] + (uint32_t)(r * FSTR + cg) * 2, kb + off);
                cp16(v_u[buf ^ 1] + (uint32_t)(r * FSTR + cg) * 2, vb + off);
            }
            CP_COMMIT();
            CP_WAIT1();
        } else {
            CP_WAIT0();
        }
        __syncthreads();

        if (t == 0) {
            #pragma unroll
            for (int ks = 0; ks < 4; ks++)
                ldm4(qf[ks], q_u + (uint32_t)((m0 + (lane & 15)) * FSTR
                         + ks * 16 + ((lane >> 4) << 3)) * 2);
        }

        // ---- S = Q @ K^T ----
        float s[8][4];
        #pragma unroll
        for (int ni = 0; ni < 8; ni++)
            #pragma unroll
            for (int j = 0; j < 4; j++) s[ni][j] = 0.f;

        #pragma unroll
        for (int ks = 0; ks < 4; ks++) {
            const int k0 = ks * 16;
            #pragma unroll
            for (int np = 0; np < 4; np++) {
                uint32_t bf[4];
                const uint32_t bd = k_u[buf] +
                    (uint32_t)((np * 16 + (lane & 7) + ((lane >> 4) << 3)) * FSTR
                               + k0 + (((lane >> 3) & 1) << 3)) * 2;
                ldm4(bf, bd);
                mma16(s[2 * np],     qf[ks], bf[0], bf[1]);
                mma16(s[2 * np + 1], qf[ks], bf[2], bf[3]);
            }
        }

        // ---- online softmax in exp2 domain ----
        #pragma unroll
        for (int ni = 0; ni < 8; ni++)
            #pragma unroll
            for (int j = 0; j < 4; j++) s[ni][j] *= SC_L2E;

        float mx0 = -1e30f, mx1 = -1e30f;
        #pragma unroll
        for (int ni = 0; ni < 8; ni++) {
            mx0 = fmaxf(mx0, fmaxf(s[ni][0], s[ni][1]));
            mx1 = fmaxf(mx1, fmaxf(s[ni][2], s[ni][3]));
        }
        mx0 = fmaxf(mx0, __shfl_xor_sync(0xffffffffu, mx0, 1));
        mx0 = fmaxf(mx0, __shfl_xor_sync(0xffffffffu, mx0, 2));
        mx1 = fmaxf(mx1, __shfl_xor_sync(0xffffffffu, mx1, 1));
        mx1 = fmaxf(mx1, __shfl_xor_sync(0xffffffffu, mx1, 2));

        const float mn0 = fmaxf(mrow[0], mx0);
        const float mn1 = fmaxf(mrow[1], mx1);
        const float al0 = ex2(mrow[0] - mn0);
        const float al1 = ex2(mrow[1] - mn1);
        mrow[0] = mn0; mrow[1] = mn1;

        float sum0 = 0.f, sum1 = 0.f;
        #pragma unroll
        for (int ni = 0; ni < 8; ni++) {
            s[ni][0] = ex2(s[ni][0] - mn0); sum0 += s[ni][0];
            s[ni][1] = ex2(s[ni][1] - mn0); sum0 += s[ni][1];
            s[ni][2] = ex2(s[ni][2] - mn1); sum1 += s[ni][2];
            s[ni][3] = ex2(s[ni][3] - mn1); sum1 += s[ni][3];
        }
        sum0 += __shfl_xor_sync(0xffffffffu, sum0, 1);
        sum0 += __shfl_xor_sync(0xffffffffu, sum0, 2);
        sum1 += __shfl_xor_sync(0xffffffffu, sum1, 1);
        sum1 += __shfl_xor_sync(0xffffffffu, sum1, 2);
        lrow[0] = lrow[0] * al0 + sum0;
        lrow[1] = lrow[1] * al1 + sum1;

        if (__any_sync(0xffffffffu, (al0 != 1.f) | (al1 != 1.f))) {
            #pragma unroll
            for (int ni = 0; ni < 8; ni++) {
                o[ni][0] *= al0; o[ni][1] *= al0;
                o[ni][2] *= al1; o[ni][3] *= al1;
            }
        }

        // ---- O += P @ V : P A-fragments packed directly from S C-frags ----
        #pragma unroll
        for (int ks = 0; ks < 4; ks++) {
            uint32_t pf[4];
            asm("cvt.rn.f16x2.f32 %0, %1, %2;" : "=r"(pf[0])
                : "f"(s[2 * ks][1]),     "f"(s[2 * ks][0]));
            asm("cvt.rn.f16x2.f32 %0, %1, %2;" : "=r"(pf[1])
                : "f"(s[2 * ks][3]),     "f"(s[2 * ks][2]));
            asm("cvt.rn.f16x2.f32 %0, %1, %2;" : "=r"(pf[2])
                : "f"(s[2 * ks + 1][1]), "f"(s[2 * ks + 1][0]));
            asm("cvt.rn.f16x2.f32 %0, %1, %2;" : "=r"(pf[3])
                : "f"(s[2 * ks + 1][3]), "f"(s[2 * ks + 1][2]));
            #pragma unroll
            for (int np = 0; np < 4; np++) {
                uint32_t vf[4];
                const uint32_t vd = v_u[buf] +
                    (uint32_t)((ks * 16 + (lane & 7) + (((lane >> 3) & 1) << 3)) * FSTR
                               + np * 16 + ((lane >> 4) << 3)) * 2;
                ldm4t(vf, vd);
                mma16(o[2 * np],     pf, vf[0], vf[1]);
                mma16(o[2 * np + 1], pf, vf[2], vf[3]);
            }
        }
        __syncthreads();
    }

    const float inv0 = 1.f / lrow[0];
    const float inv1 = 1.f / lrow[1];
    const size_t n0 = (size_t)bb * SEQ + qt * 64 + m0 + qr;
    #pragma unroll
    for (int ni = 0; ni < 8; ni++) {
        const int c = h * DHEAD + ni * 8 + 2 * qc;
        *(__half2*)(out + n0 * INNER + c) =
            __floats2half2_rn(o[ni][0] * inv0, o[ni][1] * inv0);
        *(__half2*)(out + (n0 + 8) * INNER + c) =
            __floats2half2_rn(o[ni][2] * inv1, o[ni][3] * inv1);
    }
}

// ---------------------------------------------------------------------------
extern "C" void kernel_launch(void* const* d_in, const int* in_sizes, int n_in,
                              void* d_out, int out_size)
{
    const float* x     = (const float*)d_in[0];
    const float* ln_g  = (const float*)d_in[1];
    const float* ln_b  = (const float*)d_in[2];
    const float* W_qkv = (const float*)d_in[3];
    const float* b_qkv = (const float*)d_in[4];
    const float* W_out = (const float*)d_in[5];
    const float* b_out = (const float*)d_in[6];
    float* out = (float*)d_out;

    __half *xn, *qkv, *attn, *wtq, *wto;
    cudaGetSymbolAddress((void**)&xn,   g_xn);
    cudaGetSymbolAddress((void**)&qkv,  g_qkv);
    cudaGetSymbolAddress((void**)&attn, g_attn);
    cudaGetSymbolAddress((void**)&wtq,  g_wtq);
    cudaGetSymbolAddress((void**)&wto,  g_wto);

    const int flash_smem = 5 * 64 * FSTR * (int)sizeof(__half);  // 46080
    cudaFuncSetAttribute(gemm_h, cudaFuncAttributeMaxDynamicSharedMemorySize,
                         G2_SMEM);
    cudaFuncSetAttribute(gemm_o, cudaFuncAttributeMaxDynamicSharedMemorySize,
                         GO_SMEM);
    cudaFuncSetAttribute(flash_h, cudaFuncAttributeMaxDynamicSharedMemorySize,
                         flash_smem);

    // 0) fused prep: both weight transposes + LayerNorm, one launch
    prep_kernel<<<PREP_BLKS, 256>>>(W_qkv, wtq, W_out, wto,
                                    x, ln_g, ln_b, xn);

    // 1) QKV projection (fp16 mma, 256x128 tiles, BK=64, half out)
    gemm_h<<<dim3(QKV_N / 128, ROWS / 256), 256, G2_SMEM>>>(
        xn, wtq, b_qkv, qkv, QKV_N, DIM);

    // 2) attention (fp16 flash, R14 config, half out)
    flash_h<<<dim3(SEQ / 64, BATCH * HEADS), 128, flash_smem>>>(qkv, attn);

    // 3) output projection (fp16 mma, 128x128 tiles, BK=64, 3-stage, fp32)
    gemm_o<<<dim3(DIM / 128, ROWS / 128), 256, GO_SMEM>>>(
        attn, wto, b_out, out, DIM, INNER);
}